// round 11
// baseline (speedup 1.0000x reference)
#include <cuda_runtime.h>
#include <cuda_fp16.h>
#include <cuda_bf16.h>

#define NU 100000
#define NI 50000
#define NT 150000          // NU + NI
#define EE 4000000
#define DD 64
#define BB 4096

#define SCAN_B 1024
#define NBLK_SCAN ((NT + SCAN_B - 1) / SCAN_B)   // 147

#define TB 256
#define HIST_BLOCKS ((EE / 8 + TB - 1) / TB)      // 1954 (8 edges/thread)
#define INIT_BLOCKS ((NT * 16 + TB - 1) / TB)     // 9375
#define FILL_BLOCKS ((EE / 8 + TB - 1) / TB)      // 1954 (8 edges/thread)

// ---- scratch (device globals: allocation-free) ----
__device__ __align__(256) __half g_m0[NT * DD];   // RAW e0 in fp16 (no dis scaling)
__device__ __align__(256) __half g_m1[NT * DD];   // dis-scaled mirrors: m1 = dis*h1
__device__ __align__(256) __half g_m2[NT * DD];   // m2 = dis*h2
__device__ __align__(256) float  g_dis[NT];       // d^{-1/2}
__device__ __align__(256) float  g_dsq[NT];       // d^{+1/2}  (0 if deg==0)
__device__ __align__(256) int    g_deg[NT];
__device__ __align__(256) int    g_rowptr[NT + 1];
__device__ __align__(256) int    g_cursor[NT];
__device__ __align__(256) int    g_bsum[NBLK_SCAN];
__device__ __align__(256) int    g_col[EE];       // CSR columns

__device__ __forceinline__ int2 pack_half4(float4 s) {
    __half2 p0 = __floats2half2_rn(s.x, s.y);
    __half2 p1 = __floats2half2_rn(s.z, s.w);
    return make_int2(*reinterpret_cast<int*>(&p0), *reinterpret_cast<int*>(&p1));
}

// Fused: edge-row histogram (atomic-latency-bound) + raw m0 init (DRAM-bound).
// Disjoint block ranges co-resident on SMs -> overlap.
__global__ void __launch_bounds__(256) k_hist_init(
        const int4* __restrict__ row4,
        const float4* __restrict__ users, const float4* __restrict__ items) {
    int b = blockIdx.x;
    if (b < HIST_BLOCKS) {
        int i = (b * blockDim.x + threadIdx.x) * 2;
        if (i < EE / 4) {
            int4 r0 = __ldg(&row4[i]);
            int4 r1 = __ldg(&row4[i + 1]);
            atomicAdd(&g_deg[r0.x], 1);
            atomicAdd(&g_deg[r0.y], 1);
            atomicAdd(&g_deg[r0.z], 1);
            atomicAdd(&g_deg[r0.w], 1);
            atomicAdd(&g_deg[r1.x], 1);
            atomicAdd(&g_deg[r1.y], 1);
            atomicAdd(&g_deg[r1.z], 1);
            atomicAdd(&g_deg[r1.w], 1);
        }
    } else {
        int i = (b - HIST_BLOCKS) * blockDim.x + threadIdx.x;   // over NT*16
        if (i < NT * 16) {
            float4 x = (i < NU * 16) ? __ldg(&users[i])
                                     : __ldg(&items[i - NU * 16]);
            reinterpret_cast<int2*>(g_m0)[i] = pack_half4(x);
        }
    }
}

// scan step 1 + compute dis/dsq
__global__ void k_scan1() {
    __shared__ int sh[SCAN_B];
    int i = blockIdx.x * SCAN_B + threadIdx.x;
    int v = (i < NT) ? g_deg[i] : 0;
    if (i < NT) {
        g_dis[i] = (v > 0) ? rsqrtf((float)v) : 0.0f;
        g_dsq[i] = (v > 0) ? sqrtf((float)v)  : 0.0f;
    }
    sh[threadIdx.x] = v;
    __syncthreads();
    for (int off = 1; off < SCAN_B; off <<= 1) {
        int x = (threadIdx.x >= off) ? sh[threadIdx.x - off] : 0;
        __syncthreads();
        sh[threadIdx.x] += x;
        __syncthreads();
    }
    int incl = sh[threadIdx.x];
    if (i < NT) g_rowptr[i] = incl - v;
    if (threadIdx.x == SCAN_B - 1) g_bsum[blockIdx.x] = incl;
}

// parallel exclusive scan of the 147 block sums (single block)
__global__ void k_scan2() {
    __shared__ int sh[256];
    int t = threadIdx.x;
    int v = (t < NBLK_SCAN) ? g_bsum[t] : 0;
    sh[t] = v;
    __syncthreads();
    for (int off = 1; off < 256; off <<= 1) {
        int x = (t >= off) ? sh[t - off] : 0;
        __syncthreads();
        sh[t] += x;
        __syncthreads();
    }
    if (t < NBLK_SCAN) g_bsum[t] = sh[t] - v;   // exclusive
}

// finalize rowptr + cursor
__global__ void k_scan3() {
    int i = blockIdx.x * blockDim.x + threadIdx.x;
    if (i < NT) {
        int v = g_rowptr[i] + g_bsum[i / SCAN_B];
        g_rowptr[i] = v;
        g_cursor[i] = v;
        if (i == 0) g_rowptr[NT] = EE;
    }
}

// fill CSR columns, 8 edges/thread
__global__ void __launch_bounds__(256) k_fill(
        const int4* __restrict__ row4, const int4* __restrict__ col4) {
    int i = (blockIdx.x * blockDim.x + threadIdx.x) * 2;
    if (i < EE / 4) {
        int4 r0 = __ldg(&row4[i]);
        int4 r1 = __ldg(&row4[i + 1]);
        int4 c0 = __ldg(&col4[i]);
        int4 c1 = __ldg(&col4[i + 1]);
        int p0 = atomicAdd(&g_cursor[r0.x], 1);
        int p1 = atomicAdd(&g_cursor[r0.y], 1);
        int p2 = atomicAdd(&g_cursor[r0.z], 1);
        int p3 = atomicAdd(&g_cursor[r0.w], 1);
        int p4 = atomicAdd(&g_cursor[r1.x], 1);
        int p5 = atomicAdd(&g_cursor[r1.y], 1);
        int p6 = atomicAdd(&g_cursor[r1.z], 1);
        int p7 = atomicAdd(&g_cursor[r1.w], 1);
        g_col[p0] = c0.x;
        g_col[p1] = c0.y;
        g_col[p2] = c0.z;
        g_col[p3] = c0.w;
        g_col[p4] = c1.x;
        g_col[p5] = c1.y;
        g_col[p6] = c1.z;
        g_col[p7] = c1.w;
    }
}

// SpMM hop 0: weighted by dis[c] (broadcast 4B load, L2-resident table).
// m1[r] = dis_r^2 * sum_c dis_c * m0_raw[c]
__global__ void __launch_bounds__(256) k_spmm0() {
    int t = blockIdx.x * blockDim.x + threadIdx.x;
    int r = t >> 4;
    if (r >= NT) return;
    int lane = t & 15;

    const int2* __restrict__ srcm = (const int2*)g_m0;
    int beg = g_rowptr[r];
    int end = g_rowptr[r + 1];
    const int* __restrict__ col = g_col;

    float4 s = make_float4(0.f, 0.f, 0.f, 0.f);
    int i = beg;
    for (; i + 3 < end; i += 4) {
        int c0 = __ldg(&col[i]);
        int c1 = __ldg(&col[i + 1]);
        int c2 = __ldg(&col[i + 2]);
        int c3 = __ldg(&col[i + 3]);
        float w0 = __ldg(&g_dis[c0]);
        float w1 = __ldg(&g_dis[c1]);
        float w2 = __ldg(&g_dis[c2]);
        float w3 = __ldg(&g_dis[c3]);
        int2 u0 = __ldg(&srcm[c0 * 16 + lane]);
        int2 u1 = __ldg(&srcm[c1 * 16 + lane]);
        int2 u2 = __ldg(&srcm[c2 * 16 + lane]);
        int2 u3 = __ldg(&srcm[c3 * 16 + lane]);
        float2 a0 = __half22float2(*reinterpret_cast<__half2*>(&u0.x));
        float2 b0 = __half22float2(*reinterpret_cast<__half2*>(&u0.y));
        float2 a1 = __half22float2(*reinterpret_cast<__half2*>(&u1.x));
        float2 b1 = __half22float2(*reinterpret_cast<__half2*>(&u1.y));
        float2 a2 = __half22float2(*reinterpret_cast<__half2*>(&u2.x));
        float2 b2 = __half22float2(*reinterpret_cast<__half2*>(&u2.y));
        float2 a3 = __half22float2(*reinterpret_cast<__half2*>(&u3.x));
        float2 b3 = __half22float2(*reinterpret_cast<__half2*>(&u3.y));
        s.x = fmaf(w0, a0.x, s.x); s.y = fmaf(w0, a0.y, s.y);
        s.z = fmaf(w0, b0.x, s.z); s.w = fmaf(w0, b0.y, s.w);
        s.x = fmaf(w1, a1.x, s.x); s.y = fmaf(w1, a1.y, s.y);
        s.z = fmaf(w1, b1.x, s.z); s.w = fmaf(w1, b1.y, s.w);
        s.x = fmaf(w2, a2.x, s.x); s.y = fmaf(w2, a2.y, s.y);
        s.z = fmaf(w2, b2.x, s.z); s.w = fmaf(w2, b2.y, s.w);
        s.x = fmaf(w3, a3.x, s.x); s.y = fmaf(w3, a3.y, s.y);
        s.z = fmaf(w3, b3.x, s.z); s.w = fmaf(w3, b3.y, s.w);
    }
    for (; i < end; i++) {
        int c = __ldg(&col[i]);
        float w = __ldg(&g_dis[c]);
        int2 u = __ldg(&srcm[c * 16 + lane]);
        float2 a = __half22float2(*reinterpret_cast<__half2*>(&u.x));
        float2 b = __half22float2(*reinterpret_cast<__half2*>(&u.y));
        s.x = fmaf(w, a.x, s.x); s.y = fmaf(w, a.y, s.y);
        s.z = fmaf(w, b.x, s.z); s.w = fmaf(w, b.y, s.w);
    }

    float dr = g_dis[r];
    float f = dr * dr;
    reinterpret_cast<int2*>(g_m1)[r * 16 + lane] =
        pack_half4(make_float4(f * s.x, f * s.y, f * s.z, f * s.w));
}

// SpMM hop 1: unweighted sum of dis-scaled m1. m2[r] = dis_r^2 * sum m1[c].
__global__ void __launch_bounds__(256) k_spmm1() {
    int t = blockIdx.x * blockDim.x + threadIdx.x;
    int r = t >> 4;
    if (r >= NT) return;
    int lane = t & 15;

    const int2* __restrict__ srcm = (const int2*)g_m1;
    int beg = g_rowptr[r];
    int end = g_rowptr[r + 1];
    const int* __restrict__ col = g_col;

    float4 s = make_float4(0.f, 0.f, 0.f, 0.f);
    int i = beg;
    for (; i + 3 < end; i += 4) {
        int c0 = __ldg(&col[i]);
        int c1 = __ldg(&col[i + 1]);
        int c2 = __ldg(&col[i + 2]);
        int c3 = __ldg(&col[i + 3]);
        int2 u0 = __ldg(&srcm[c0 * 16 + lane]);
        int2 u1 = __ldg(&srcm[c1 * 16 + lane]);
        int2 u2 = __ldg(&srcm[c2 * 16 + lane]);
        int2 u3 = __ldg(&srcm[c3 * 16 + lane]);
        float2 a0 = __half22float2(*reinterpret_cast<__half2*>(&u0.x));
        float2 b0 = __half22float2(*reinterpret_cast<__half2*>(&u0.y));
        float2 a1 = __half22float2(*reinterpret_cast<__half2*>(&u1.x));
        float2 b1 = __half22float2(*reinterpret_cast<__half2*>(&u1.y));
        float2 a2 = __half22float2(*reinterpret_cast<__half2*>(&u2.x));
        float2 b2 = __half22float2(*reinterpret_cast<__half2*>(&u2.y));
        float2 a3 = __half22float2(*reinterpret_cast<__half2*>(&u3.x));
        float2 b3 = __half22float2(*reinterpret_cast<__half2*>(&u3.y));
        s.x += (a0.x + a1.x) + (a2.x + a3.x);
        s.y += (a0.y + a1.y) + (a2.y + a3.y);
        s.z += (b0.x + b1.x) + (b2.x + b3.x);
        s.w += (b0.y + b1.y) + (b2.y + b3.y);
    }
    for (; i < end; i++) {
        int c = __ldg(&col[i]);
        int2 u = __ldg(&srcm[c * 16 + lane]);
        float2 a = __half22float2(*reinterpret_cast<__half2*>(&u.x));
        float2 b = __half22float2(*reinterpret_cast<__half2*>(&u.y));
        s.x += a.x; s.y += a.y; s.z += b.x; s.w += b.y;
    }

    float dr = g_dis[r];
    float f = dr * dr;
    reinterpret_cast<int2*>(g_m2)[r * 16 + lane] =
        pack_half4(make_float4(f * s.x, f * s.y, f * s.z, f * s.w));
}

// Fused hop-3 + gather: one warp per output slot (b, side).
// S = sum_{c in N(r)} m2[c];  out = 0.25*(e0[r] + dsq*(m1[r]+m2[r]) + dis[r]*S)
__global__ void __launch_bounds__(256) k_gather_fused(
        const float* __restrict__ users, const float* __restrict__ items,
        const int* __restrict__ uid, const int* __restrict__ iid,
        float2* __restrict__ out) {
    int t = blockIdx.x * blockDim.x + threadIdx.x;
    int slot = t >> 5;                 // 8192 slots
    if (slot >= BB * 2) return;
    int lane = t & 31;
    int b = slot >> 1, side = slot & 1;

    int node;
    const float2* e0;
    if (!side) { int u = __ldg(&uid[b]); node = u;      e0 = (const float2*)users + u * 32; }
    else       { int v = __ldg(&iid[b]); node = NU + v; e0 = (const float2*)items + v * 32; }

    int beg = g_rowptr[node];
    int end = g_rowptr[node + 1];
    const int* __restrict__ col = g_col;
    const __half2* __restrict__ m2h = (const __half2*)g_m2;

    float2 S = make_float2(0.f, 0.f);
    int i = beg;
    for (; i + 3 < end; i += 4) {
        int c0 = __ldg(&col[i]);
        int c1 = __ldg(&col[i + 1]);
        int c2 = __ldg(&col[i + 2]);
        int c3 = __ldg(&col[i + 3]);
        float2 x0 = __half22float2(__ldg(&m2h[c0 * 32 + lane]));
        float2 x1 = __half22float2(__ldg(&m2h[c1 * 32 + lane]));
        float2 x2 = __half22float2(__ldg(&m2h[c2 * 32 + lane]));
        float2 x3 = __half22float2(__ldg(&m2h[c3 * 32 + lane]));
        S.x += (x0.x + x1.x) + (x2.x + x3.x);
        S.y += (x0.y + x1.y) + (x2.y + x3.y);
    }
    for (; i < end; i++) {
        int c = __ldg(&col[i]);
        float2 x = __half22float2(__ldg(&m2h[c * 32 + lane]));
        S.x += x.x; S.y += x.y;
    }

    float dr = g_dis[node];
    float dq = g_dsq[node];
    float2 v0 = __ldg(&e0[lane]);
    float2 a1 = __half22float2(((const __half2*)g_m1)[node * 32 + lane]);
    float2 a2 = __half22float2(((const __half2*)g_m2)[node * 32 + lane]);

    float2 o;
    o.x = 0.25f * (v0.x + dq * (a1.x + a2.x) + dr * S.x);
    o.y = 0.25f * (v0.y + dq * (a1.y + a2.y) + dr * S.y);
    out[slot * 32 + lane] = o;         // = b*64 + side*32 + lane
}

extern "C" void kernel_launch(void* const* d_in, const int* in_sizes, int n_in,
                              void* d_out, int out_size) {
    const float* users = (const float*)d_in[0];
    const float* items = (const float*)d_in[1];
    const int*   erow  = (const int*)d_in[2];
    const int*   ecol  = (const int*)d_in[3];
    const int*   uid   = (const int*)d_in[4];
    const int*   iid   = (const int*)d_in[5];
    float2*      out   = (float2*)d_out;

    void* degp = nullptr;
    cudaGetSymbolAddress(&degp, g_deg);
    cudaMemsetAsync(degp, 0, NT * sizeof(int));

    k_hist_init<<<HIST_BLOCKS + INIT_BLOCKS, TB>>>(
        (const int4*)erow, (const float4*)users, (const float4*)items);
    k_scan1 <<<NBLK_SCAN, SCAN_B>>>();
    k_scan2 <<<1, 256>>>();
    k_scan3 <<<(NT + TB - 1) / TB, TB>>>();
    k_fill  <<<FILL_BLOCKS, TB>>>((const int4*)erow, (const int4*)ecol);

    int spmm_threads = NT * 16;
    k_spmm0<<<(spmm_threads + TB - 1) / TB, TB>>>();
    k_spmm1<<<(spmm_threads + TB - 1) / TB, TB>>>();

    k_gather_fused<<<(BB * 2 * 32 + TB - 1) / TB, TB>>>(users, items, uid, iid, out);
}

// round 12
// speedup vs baseline: 1.0616x; 1.0616x over previous
#include <cuda_runtime.h>
#include <cuda_fp16.h>
#include <cuda_bf16.h>

#define NU 100000
#define NI 50000
#define NT 150000          // NU + NI
#define EE 4000000
#define DD 64
#define BB 4096

#define SCAN_B 1024
#define NBLK_SCAN ((NT + SCAN_B - 1) / SCAN_B)   // 147

#define TB 256
#define HIST_BLOCKS ((EE / 8 + TB - 1) / TB)      // 1954 (8 edges/thread)
#define FILL_BLOCKS ((EE / 8 + TB - 1) / TB)      // 1954 (8 edges/thread)
#define INIT_BLOCKS ((NT * 16 + TB - 1) / TB)     // 9375

// ---- scratch (device globals: allocation-free) ----
__device__ __align__(256) __half g_m0[NT * DD];   // fp16 scaled mirrors (m0 = dis*e0, m_{k+1} = dis^2*S)
__device__ __align__(256) __half g_m1[NT * DD];
__device__ __align__(256) __half g_m2[NT * DD];
__device__ __align__(256) float  g_dis[NT];       // d^{-1/2}
__device__ __align__(256) float  g_dsq[NT];       // d^{+1/2}  (0 if deg==0)
__device__ __align__(256) int    g_deg[NT];
__device__ __align__(256) int    g_rowptr[NT + 1]; // partial; final = rowptr[r]+bsum[r>>10]
__device__ __align__(256) int    g_bsum[NBLK_SCAN];
__device__ __align__(256) unsigned short g_pos[EE]; // per-edge within-row index (from hist)
__device__ __align__(256) int    g_col[EE];       // CSR columns

__device__ __forceinline__ int rp(int r) {        // final rowptr
    return g_rowptr[r] + __ldg(&g_bsum[r >> 10]);
}

__device__ __forceinline__ int2 pack_half4(float4 s) {
    __half2 p0 = __floats2half2_rn(s.x, s.y);
    __half2 p1 = __floats2half2_rn(s.z, s.w);
    return make_int2(*reinterpret_cast<int*>(&p0), *reinterpret_cast<int*>(&p1));
}

// histogram of edge rows, 8 edges/thread; records each edge's within-row slot
__global__ void __launch_bounds__(256) k_hist(const int4* __restrict__ row4) {
    int i = (blockIdx.x * blockDim.x + threadIdx.x) * 2;   // int4 index (even)
    if (i < EE / 4) {
        int4 r0 = __ldg(&row4[i]);
        int4 r1 = __ldg(&row4[i + 1]);
        unsigned p0 = atomicAdd(&g_deg[r0.x], 1);
        unsigned p1 = atomicAdd(&g_deg[r0.y], 1);
        unsigned p2 = atomicAdd(&g_deg[r0.z], 1);
        unsigned p3 = atomicAdd(&g_deg[r0.w], 1);
        unsigned p4 = atomicAdd(&g_deg[r1.x], 1);
        unsigned p5 = atomicAdd(&g_deg[r1.y], 1);
        unsigned p6 = atomicAdd(&g_deg[r1.z], 1);
        unsigned p7 = atomicAdd(&g_deg[r1.w], 1);
        uint4 pk;
        pk.x = (p0 & 0xFFFF) | (p1 << 16);
        pk.y = (p2 & 0xFFFF) | (p3 << 16);
        pk.z = (p4 & 0xFFFF) | (p5 << 16);
        pk.w = (p6 & 0xFFFF) | (p7 << 16);
        *reinterpret_cast<uint4*>(&g_pos[i * 4]) = pk;     // 16B aligned: i even
    }
}

// scan step 1 + compute dis/dsq; writes blockwise-exclusive rowptr
__global__ void k_scan1() {
    __shared__ int sh[SCAN_B];
    int i = blockIdx.x * SCAN_B + threadIdx.x;
    int v = (i < NT) ? g_deg[i] : 0;
    if (i < NT) {
        g_dis[i] = (v > 0) ? rsqrtf((float)v) : 0.0f;
        g_dsq[i] = (v > 0) ? sqrtf((float)v)  : 0.0f;
    }
    sh[threadIdx.x] = v;
    __syncthreads();
    for (int off = 1; off < SCAN_B; off <<= 1) {
        int x = (threadIdx.x >= off) ? sh[threadIdx.x - off] : 0;
        __syncthreads();
        sh[threadIdx.x] += x;
        __syncthreads();
    }
    int incl = sh[threadIdx.x];
    if (i < NT) g_rowptr[i] = incl - v;
    if (threadIdx.x == SCAN_B - 1) g_bsum[blockIdx.x] = incl;
}

// exclusive scan of the 147 block sums; patch rowptr[NT] so rp(NT)==EE
__global__ void k_scan2() {
    __shared__ int sh[256];
    int t = threadIdx.x;
    int v = (t < NBLK_SCAN) ? g_bsum[t] : 0;
    sh[t] = v;
    __syncthreads();
    for (int off = 1; off < 256; off <<= 1) {
        int x = (t >= off) ? sh[t - off] : 0;
        __syncthreads();
        sh[t] += x;
        __syncthreads();
    }
    if (t < NBLK_SCAN) {
        int excl = sh[t] - v;
        g_bsum[t] = excl;
        if (t == NBLK_SCAN - 1) g_rowptr[NT] = EE - excl;   // NT>>10 == NBLK_SCAN-1
    }
}

// Fused atomic-FREE CSR fill + m0-init (disjoint block ranges, co-resident).
// fill: g_col[rp(r) + pos[e]] = col[e]  — independent scattered stores.
__global__ void __launch_bounds__(256) k_fill_init(
        const int4* __restrict__ row4, const int4* __restrict__ col4,
        const float4* __restrict__ users, const float4* __restrict__ items) {
    int b = blockIdx.x;
    if (b < FILL_BLOCKS) {
        int i = (b * blockDim.x + threadIdx.x) * 2;         // int4 index (even)
        if (i < EE / 4) {
            int4 r0 = __ldg(&row4[i]);
            int4 r1 = __ldg(&row4[i + 1]);
            int4 c0 = __ldg(&col4[i]);
            int4 c1 = __ldg(&col4[i + 1]);
            uint4 pk = *reinterpret_cast<const uint4*>(&g_pos[i * 4]);
            int p0 = rp(r0.x) + (pk.x & 0xFFFF);
            int p1 = rp(r0.y) + (pk.x >> 16);
            int p2 = rp(r0.z) + (pk.y & 0xFFFF);
            int p3 = rp(r0.w) + (pk.y >> 16);
            int p4 = rp(r1.x) + (pk.z & 0xFFFF);
            int p5 = rp(r1.y) + (pk.z >> 16);
            int p6 = rp(r1.z) + (pk.w & 0xFFFF);
            int p7 = rp(r1.w) + (pk.w >> 16);
            g_col[p0] = c0.x;
            g_col[p1] = c0.y;
            g_col[p2] = c0.z;
            g_col[p3] = c0.w;
            g_col[p4] = c1.x;
            g_col[p5] = c1.y;
            g_col[p6] = c1.z;
            g_col[p7] = c1.w;
        }
    } else {
        int i = (b - FILL_BLOCKS) * blockDim.x + threadIdx.x;   // over NT*16
        if (i < NT * 16) {
            int node = i >> 4;
            float d = g_dis[node];
            float4 x = (node < NU) ? __ldg(&users[i])
                                   : __ldg(&items[i - NU * 16]);
            reinterpret_cast<int2*>(g_m0)[i] =
                pack_half4(make_float4(d * x.x, d * x.y, d * x.z, d * x.w));
        }
    }
}

// CSR SpMM: 16 threads/row; unweighted segment-sum of scaled fp16 mirrors.
// Stores next scaled mirror: m_{k+1} = dis[r]^2 * S.
__global__ void __launch_bounds__(256) k_spmm(int hop) {
    int t = blockIdx.x * blockDim.x + threadIdx.x;
    int r = t >> 4;
    if (r >= NT) return;
    int lane = t & 15;

    const int2* __restrict__ srcm = (hop == 0) ? (const int2*)g_m0 : (const int2*)g_m1;
    int2* dstm                    = (hop == 0) ? (int2*)g_m1       : (int2*)g_m2;

    int beg = rp(r);
    int end = rp(r + 1);
    const int* __restrict__ col = g_col;

    float4 s = make_float4(0.f, 0.f, 0.f, 0.f);
    int i = beg;
    for (; i + 3 < end; i += 4) {
        int c0 = __ldg(&col[i]);
        int c1 = __ldg(&col[i + 1]);
        int c2 = __ldg(&col[i + 2]);
        int c3 = __ldg(&col[i + 3]);
        int2 u0 = __ldg(&srcm[c0 * 16 + lane]);
        int2 u1 = __ldg(&srcm[c1 * 16 + lane]);
        int2 u2 = __ldg(&srcm[c2 * 16 + lane]);
        int2 u3 = __ldg(&srcm[c3 * 16 + lane]);
        float2 a0 = __half22float2(*reinterpret_cast<__half2*>(&u0.x));
        float2 b0 = __half22float2(*reinterpret_cast<__half2*>(&u0.y));
        float2 a1 = __half22float2(*reinterpret_cast<__half2*>(&u1.x));
        float2 b1 = __half22float2(*reinterpret_cast<__half2*>(&u1.y));
        float2 a2 = __half22float2(*reinterpret_cast<__half2*>(&u2.x));
        float2 b2 = __half22float2(*reinterpret_cast<__half2*>(&u2.y));
        float2 a3 = __half22float2(*reinterpret_cast<__half2*>(&u3.x));
        float2 b3 = __half22float2(*reinterpret_cast<__half2*>(&u3.y));
        s.x += (a0.x + a1.x) + (a2.x + a3.x);
        s.y += (a0.y + a1.y) + (a2.y + a3.y);
        s.z += (b0.x + b1.x) + (b2.x + b3.x);
        s.w += (b0.y + b1.y) + (b2.y + b3.y);
    }
    for (; i < end; i++) {
        int c = __ldg(&col[i]);
        int2 u = __ldg(&srcm[c * 16 + lane]);
        float2 a = __half22float2(*reinterpret_cast<__half2*>(&u.x));
        float2 b = __half22float2(*reinterpret_cast<__half2*>(&u.y));
        s.x += a.x; s.y += a.y; s.z += b.x; s.w += b.y;
    }

    float dr = g_dis[r];
    float f = dr * dr;
    reinterpret_cast<int2*>(dstm)[r * 16 + lane] =
        pack_half4(make_float4(f * s.x, f * s.y, f * s.z, f * s.w));
}

// Fused hop-3 + gather: one warp per output slot (b, side).
// S = sum_{c in N(r)} m2[c];  out = 0.25*(e0[r] + dsq*(m1[r]+m2[r]) + dis[r]*S)
__global__ void __launch_bounds__(256) k_gather_fused(
        const float* __restrict__ users, const float* __restrict__ items,
        const int* __restrict__ uid, const int* __restrict__ iid,
        float2* __restrict__ out) {
    int t = blockIdx.x * blockDim.x + threadIdx.x;
    int slot = t >> 5;                 // 8192 slots
    if (slot >= BB * 2) return;
    int lane = t & 31;
    int b = slot >> 1, side = slot & 1;

    int node;
    const float2* e0;
    if (!side) { int u = __ldg(&uid[b]); node = u;      e0 = (const float2*)users + u * 32; }
    else       { int v = __ldg(&iid[b]); node = NU + v; e0 = (const float2*)items + v * 32; }

    int beg = rp(node);
    int end = rp(node + 1);
    const int* __restrict__ col = g_col;
    const __half2* __restrict__ m2h = (const __half2*)g_m2;

    float2 S = make_float2(0.f, 0.f);
    int i = beg;
    for (; i + 3 < end; i += 4) {
        int c0 = __ldg(&col[i]);
        int c1 = __ldg(&col[i + 1]);
        int c2 = __ldg(&col[i + 2]);
        int c3 = __ldg(&col[i + 3]);
        float2 x0 = __half22float2(__ldg(&m2h[c0 * 32 + lane]));
        float2 x1 = __half22float2(__ldg(&m2h[c1 * 32 + lane]));
        float2 x2 = __half22float2(__ldg(&m2h[c2 * 32 + lane]));
        float2 x3 = __half22float2(__ldg(&m2h[c3 * 32 + lane]));
        S.x += (x0.x + x1.x) + (x2.x + x3.x);
        S.y += (x0.y + x1.y) + (x2.y + x3.y);
    }
    for (; i < end; i++) {
        int c = __ldg(&col[i]);
        float2 x = __half22float2(__ldg(&m2h[c * 32 + lane]));
        S.x += x.x; S.y += x.y;
    }

    float dr = g_dis[node];
    float dq = g_dsq[node];
    float2 v0 = __ldg(&e0[lane]);
    float2 a1 = __half22float2(((const __half2*)g_m1)[node * 32 + lane]);
    float2 a2 = __half22float2(((const __half2*)g_m2)[node * 32 + lane]);

    float2 o;
    o.x = 0.25f * (v0.x + dq * (a1.x + a2.x) + dr * S.x);
    o.y = 0.25f * (v0.y + dq * (a1.y + a2.y) + dr * S.y);
    out[slot * 32 + lane] = o;         // = b*64 + side*32 + lane
}

extern "C" void kernel_launch(void* const* d_in, const int* in_sizes, int n_in,
                              void* d_out, int out_size) {
    const float* users = (const float*)d_in[0];
    const float* items = (const float*)d_in[1];
    const int*   erow  = (const int*)d_in[2];
    const int*   ecol  = (const int*)d_in[3];
    const int*   uid   = (const int*)d_in[4];
    const int*   iid   = (const int*)d_in[5];
    float2*      out   = (float2*)d_out;

    void* degp = nullptr;
    cudaGetSymbolAddress(&degp, g_deg);
    cudaMemsetAsync(degp, 0, NT * sizeof(int));

    k_hist  <<<HIST_BLOCKS, TB>>>((const int4*)erow);
    k_scan1 <<<NBLK_SCAN, SCAN_B>>>();
    k_scan2 <<<1, 256>>>();
    k_fill_init<<<FILL_BLOCKS + INIT_BLOCKS, TB>>>(
        (const int4*)erow, (const int4*)ecol,
        (const float4*)users, (const float4*)items);

    int spmm_threads = NT * 16;
    k_spmm<<<(spmm_threads + TB - 1) / TB, TB>>>(0);
    k_spmm<<<(spmm_threads + TB - 1) / TB, TB>>>(1);

    k_gather_fused<<<(BB * 2 * 32 + TB - 1) / TB, TB>>>(users, items, uid, iid, out);
}

// round 13
// speedup vs baseline: 1.0730x; 1.0108x over previous
#include <cuda_runtime.h>
#include <cuda_fp16.h>
#include <cuda_bf16.h>

#define NU 100000
#define NI 50000
#define NT 150000          // NU + NI
#define EE 4000000
#define DD 64
#define BB 4096

#define SCAN_B 1024
#define NBLK_SCAN ((NT + SCAN_B - 1) / SCAN_B)   // 147

#define TB 256
#define HIST_BLOCKS ((EE / 8 + TB - 1) / TB)      // 1954 (8 edges/thread)
#define FILL_BLOCKS ((EE / 4 + TB - 1) / TB)      // 3907 (4 edges/thread)
#define INIT_BLOCKS ((NT * 16 + TB - 1) / TB)     // 9375
// interleave: groups of 17 blocks = 5 fill + 12 init
#define GROUPS 782                                 // 782*5=3910>=3907, 782*12=9384>=9375
#define MIX_BLOCKS (GROUPS * 17)                   // 13294

// ---- scratch (device globals: allocation-free) ----
__device__ __align__(256) __half g_m0[NT * DD];   // fp16 scaled mirrors (m0 = dis*e0, m_{k+1} = dis^2*S)
__device__ __align__(256) __half g_m1[NT * DD];
__device__ __align__(256) __half g_m2[NT * DD];
__device__ __align__(256) float  g_dis[NT];       // d^{-1/2}
__device__ __align__(256) float  g_dsq[NT];       // d^{+1/2}  (0 if deg==0)
__device__ __align__(256) int    g_deg[NT];
__device__ __align__(256) int    g_rowptr[NT + 1]; // partial; final = rowptr[r]+bsum[r>>10]
__device__ __align__(256) int    g_bsum[NBLK_SCAN];
__device__ __align__(256) unsigned short g_pos[EE]; // per-edge within-row index (from hist)
__device__ __align__(256) int    g_col[EE];       // CSR columns

__device__ __forceinline__ int rp(int r) {        // final rowptr
    return g_rowptr[r] + __ldg(&g_bsum[r >> 10]);
}

__device__ __forceinline__ int2 pack_half4(float4 s) {
    __half2 p0 = __floats2half2_rn(s.x, s.y);
    __half2 p1 = __floats2half2_rn(s.z, s.w);
    return make_int2(*reinterpret_cast<int*>(&p0), *reinterpret_cast<int*>(&p1));
}

// histogram of edge rows, 8 edges/thread; records each edge's within-row slot
__global__ void __launch_bounds__(256) k_hist(const int4* __restrict__ row4) {
    int i = (blockIdx.x * blockDim.x + threadIdx.x) * 2;   // int4 index (even)
    if (i < EE / 4) {
        int4 r0 = __ldg(&row4[i]);
        int4 r1 = __ldg(&row4[i + 1]);
        unsigned p0 = atomicAdd(&g_deg[r0.x], 1);
        unsigned p1 = atomicAdd(&g_deg[r0.y], 1);
        unsigned p2 = atomicAdd(&g_deg[r0.z], 1);
        unsigned p3 = atomicAdd(&g_deg[r0.w], 1);
        unsigned p4 = atomicAdd(&g_deg[r1.x], 1);
        unsigned p5 = atomicAdd(&g_deg[r1.y], 1);
        unsigned p6 = atomicAdd(&g_deg[r1.z], 1);
        unsigned p7 = atomicAdd(&g_deg[r1.w], 1);
        uint4 pk;
        pk.x = (p0 & 0xFFFF) | (p1 << 16);
        pk.y = (p2 & 0xFFFF) | (p3 << 16);
        pk.z = (p4 & 0xFFFF) | (p5 << 16);
        pk.w = (p6 & 0xFFFF) | (p7 << 16);
        *reinterpret_cast<uint4*>(&g_pos[i * 4]) = pk;     // 16B aligned: i even
    }
}

// scan step 1 + compute dis/dsq; writes blockwise-exclusive rowptr
__global__ void k_scan1() {
    __shared__ int sh[SCAN_B];
    int i = blockIdx.x * SCAN_B + threadIdx.x;
    int v = (i < NT) ? g_deg[i] : 0;
    if (i < NT) {
        g_dis[i] = (v > 0) ? rsqrtf((float)v) : 0.0f;
        g_dsq[i] = (v > 0) ? sqrtf((float)v)  : 0.0f;
    }
    sh[threadIdx.x] = v;
    __syncthreads();
    for (int off = 1; off < SCAN_B; off <<= 1) {
        int x = (threadIdx.x >= off) ? sh[threadIdx.x - off] : 0;
        __syncthreads();
        sh[threadIdx.x] += x;
        __syncthreads();
    }
    int incl = sh[threadIdx.x];
    if (i < NT) g_rowptr[i] = incl - v;
    if (threadIdx.x == SCAN_B - 1) g_bsum[blockIdx.x] = incl;
}

// exclusive scan of the 147 block sums; patch rowptr[NT] so rp(NT)==EE
__global__ void k_scan2() {
    __shared__ int sh[256];
    int t = threadIdx.x;
    int v = (t < NBLK_SCAN) ? g_bsum[t] : 0;
    sh[t] = v;
    __syncthreads();
    for (int off = 1; off < 256; off <<= 1) {
        int x = (t >= off) ? sh[t - off] : 0;
        __syncthreads();
        sh[t] += x;
        __syncthreads();
    }
    if (t < NBLK_SCAN) {
        int excl = sh[t] - v;
        g_bsum[t] = excl;
        if (t == NBLK_SCAN - 1) g_rowptr[NT] = EE - excl;   // NT>>10 == NBLK_SCAN-1
    }
}

// Fused atomic-FREE CSR fill + m0-init, roles INTERLEAVED across the grid
// (groups of 17 blocks: 5 fill + 12 init) so latency-bound fill overlaps
// DRAM-bound init in every wave.
__global__ void __launch_bounds__(256) k_fill_init(
        const int4* __restrict__ row4, const int4* __restrict__ col4,
        const float4* __restrict__ users, const float4* __restrict__ items) {
    int b = blockIdx.x;
    int g = b / 17;
    int k = b % 17;
    if (k < 5) {
        // ---- fill role: 4 edges/thread ----
        int fb = g * 5 + k;
        if (fb >= FILL_BLOCKS) return;
        int i = fb * blockDim.x + threadIdx.x;             // int4 index
        if (i < EE / 4) {
            int4 r = __ldg(&row4[i]);
            int4 c = __ldg(&col4[i]);
            uint2 pk = *reinterpret_cast<const uint2*>(&g_pos[i * 4]);
            int p0 = rp(r.x) + (pk.x & 0xFFFF);
            int p1 = rp(r.y) + (pk.x >> 16);
            int p2 = rp(r.z) + (pk.y & 0xFFFF);
            int p3 = rp(r.w) + (pk.y >> 16);
            g_col[p0] = c.x;
            g_col[p1] = c.y;
            g_col[p2] = c.z;
            g_col[p3] = c.w;
        }
    } else {
        // ---- init role ----
        int ib = g * 12 + (k - 5);
        if (ib >= INIT_BLOCKS) return;
        int i = ib * blockDim.x + threadIdx.x;             // over NT*16
        if (i < NT * 16) {
            int node = i >> 4;
            float d = g_dis[node];
            float4 x = (node < NU) ? __ldg(&users[i])
                                   : __ldg(&items[i - NU * 16]);
            reinterpret_cast<int2*>(g_m0)[i] =
                pack_half4(make_float4(d * x.x, d * x.y, d * x.z, d * x.w));
        }
    }
}

// CSR SpMM: 16 threads/row; unweighted segment-sum of scaled fp16 mirrors.
// Stores next scaled mirror: m_{k+1} = dis[r]^2 * S.
__global__ void __launch_bounds__(256) k_spmm(int hop) {
    int t = blockIdx.x * blockDim.x + threadIdx.x;
    int r = t >> 4;
    if (r >= NT) return;
    int lane = t & 15;

    const int2* __restrict__ srcm = (hop == 0) ? (const int2*)g_m0 : (const int2*)g_m1;
    int2* dstm                    = (hop == 0) ? (int2*)g_m1       : (int2*)g_m2;

    int beg = rp(r);
    int end = rp(r + 1);
    const int* __restrict__ col = g_col;

    float4 s = make_float4(0.f, 0.f, 0.f, 0.f);
    int i = beg;
    for (; i + 3 < end; i += 4) {
        int c0 = __ldg(&col[i]);
        int c1 = __ldg(&col[i + 1]);
        int c2 = __ldg(&col[i + 2]);
        int c3 = __ldg(&col[i + 3]);
        int2 u0 = __ldg(&srcm[c0 * 16 + lane]);
        int2 u1 = __ldg(&srcm[c1 * 16 + lane]);
        int2 u2 = __ldg(&srcm[c2 * 16 + lane]);
        int2 u3 = __ldg(&srcm[c3 * 16 + lane]);
        float2 a0 = __half22float2(*reinterpret_cast<__half2*>(&u0.x));
        float2 b0 = __half22float2(*reinterpret_cast<__half2*>(&u0.y));
        float2 a1 = __half22float2(*reinterpret_cast<__half2*>(&u1.x));
        float2 b1 = __half22float2(*reinterpret_cast<__half2*>(&u1.y));
        float2 a2 = __half22float2(*reinterpret_cast<__half2*>(&u2.x));
        float2 b2 = __half22float2(*reinterpret_cast<__half2*>(&u2.y));
        float2 a3 = __half22float2(*reinterpret_cast<__half2*>(&u3.x));
        float2 b3 = __half22float2(*reinterpret_cast<__half2*>(&u3.y));
        s.x += (a0.x + a1.x) + (a2.x + a3.x);
        s.y += (a0.y + a1.y) + (a2.y + a3.y);
        s.z += (b0.x + b1.x) + (b2.x + b3.x);
        s.w += (b0.y + b1.y) + (b2.y + b3.y);
    }
    for (; i < end; i++) {
        int c = __ldg(&col[i]);
        int2 u = __ldg(&srcm[c * 16 + lane]);
        float2 a = __half22float2(*reinterpret_cast<__half2*>(&u.x));
        float2 b = __half22float2(*reinterpret_cast<__half2*>(&u.y));
        s.x += a.x; s.y += a.y; s.z += b.x; s.w += b.y;
    }

    float dr = g_dis[r];
    float f = dr * dr;
    reinterpret_cast<int2*>(dstm)[r * 16 + lane] =
        pack_half4(make_float4(f * s.x, f * s.y, f * s.z, f * s.w));
}

// Fused hop-3 + gather: one warp per output slot (b, side).
// S = sum_{c in N(r)} m2[c];  out = 0.25*(e0[r] + dsq*(m1[r]+m2[r]) + dis[r]*S)
__global__ void __launch_bounds__(256) k_gather_fused(
        const float* __restrict__ users, const float* __restrict__ items,
        const int* __restrict__ uid, const int* __restrict__ iid,
        float2* __restrict__ out) {
    int t = blockIdx.x * blockDim.x + threadIdx.x;
    int slot = t >> 5;                 // 8192 slots
    if (slot >= BB * 2) return;
    int lane = t & 31;
    int b = slot >> 1, side = slot & 1;

    int node;
    const float2* e0;
    if (!side) { int u = __ldg(&uid[b]); node = u;      e0 = (const float2*)users + u * 32; }
    else       { int v = __ldg(&iid[b]); node = NU + v; e0 = (const float2*)items + v * 32; }

    int beg = rp(node);
    int end = rp(node + 1);
    const int* __restrict__ col = g_col;
    const __half2* __restrict__ m2h = (const __half2*)g_m2;

    float2 S = make_float2(0.f, 0.f);
    int i = beg;
    for (; i + 3 < end; i += 4) {
        int c0 = __ldg(&col[i]);
        int c1 = __ldg(&col[i + 1]);
        int c2 = __ldg(&col[i + 2]);
        int c3 = __ldg(&col[i + 3]);
        float2 x0 = __half22float2(__ldg(&m2h[c0 * 32 + lane]));
        float2 x1 = __half22float2(__ldg(&m2h[c1 * 32 + lane]));
        float2 x2 = __half22float2(__ldg(&m2h[c2 * 32 + lane]));
        float2 x3 = __half22float2(__ldg(&m2h[c3 * 32 + lane]));
        S.x += (x0.x + x1.x) + (x2.x + x3.x);
        S.y += (x0.y + x1.y) + (x2.y + x3.y);
    }
    for (; i < end; i++) {
        int c = __ldg(&col[i]);
        float2 x = __half22float2(__ldg(&m2h[c * 32 + lane]));
        S.x += x.x; S.y += x.y;
    }

    float dr = g_dis[node];
    float dq = g_dsq[node];
    float2 v0 = __ldg(&e0[lane]);
    float2 a1 = __half22float2(((const __half2*)g_m1)[node * 32 + lane]);
    float2 a2 = __half22float2(((const __half2*)g_m2)[node * 32 + lane]);

    float2 o;
    o.x = 0.25f * (v0.x + dq * (a1.x + a2.x) + dr * S.x);
    o.y = 0.25f * (v0.y + dq * (a1.y + a2.y) + dr * S.y);
    out[slot * 32 + lane] = o;         // = b*64 + side*32 + lane
}

extern "C" void kernel_launch(void* const* d_in, const int* in_sizes, int n_in,
                              void* d_out, int out_size) {
    const float* users = (const float*)d_in[0];
    const float* items = (const float*)d_in[1];
    const int*   erow  = (const int*)d_in[2];
    const int*   ecol  = (const int*)d_in[3];
    const int*   uid   = (const int*)d_in[4];
    const int*   iid   = (const int*)d_in[5];
    float2*      out   = (float2*)d_out;

    void* degp = nullptr;
    cudaGetSymbolAddress(&degp, g_deg);
    cudaMemsetAsync(degp, 0, NT * sizeof(int));

    k_hist  <<<HIST_BLOCKS, TB>>>((const int4*)erow);
    k_scan1 <<<NBLK_SCAN, SCAN_B>>>();
    k_scan2 <<<1, 256>>>();
    k_fill_init<<<MIX_BLOCKS, TB>>>(
        (const int4*)erow, (const int4*)ecol,
        (const float4*)users, (const float4*)items);

    int spmm_threads = NT * 16;
    k_spmm<<<(spmm_threads + TB - 1) / TB, TB>>>(0);
    k_spmm<<<(spmm_threads + TB - 1) / TB, TB>>>(1);

    k_gather_fused<<<(BB * 2 * 32 + TB - 1) / TB, TB>>>(users, items, uid, iid, out);
}